// round 11
// baseline (speedup 1.0000x reference)
#include <cuda_runtime.h>
#include <cstdint>

#define ROWS            128
#define ROW_N           262144                     // 256*32*32
#define BLOCKS_PER_ROW  32
#define SEG_N           (ROW_N / BLOCKS_PER_ROW)   // 8192 elements per block
#define THREADS         256
#define WARPS           (THREADS / 32)             // 8
#define VEC             (SEG_N / 4 / THREADS)      // 8 float4 per thread
#define GSIZE           16                         // elements per prescreen group
#define GROUPS          2                          // groups of 16 per thread
#define TOPK            5
#define EXP_N           (TOPK * GSIZE)             // 80 elements to expand
#define CAND_PER_ROW    (BLOCKS_PER_ROW * WARPS * TOPK)   // 1280 group candidates

#define FULLMASK 0xFFFFFFFFu

// Scratch (no cudaMalloc allowed). Zero-initialized device globals.
__device__ float g_cand_val[ROWS * CAND_PER_ROW];   // group max
__device__ int   g_cand_idx[ROWS * CAND_PER_ROW];   // group base index (row-relative)
__device__ int   g_row_cnt[ROWS];                   // last-block-closes-row counters

// larger value wins; equal value -> smaller index wins (jax.lax.top_k stability).
__device__ __forceinline__ bool better(float v, int i, float bv, int bi) {
    return (v > bv) || (v == bv && i < bi);
}

// Register-resident 5-way select (avoids local-memory spill from dynamic index).
__device__ __forceinline__ float get5f(const float v[TOPK], int p) {
    float r = (p == 0) ? v[0] : v[1];
    r = (p == 2) ? v[2] : r;
    r = (p == 3) ? v[3] : r;
    r = (p == 4) ? v[4] : r;
    return (p >= TOPK) ? -INFINITY : r;
}
__device__ __forceinline__ int get5i(const int v[TOPK], int p) {
    int r = (p == 0) ? v[0] : v[1];
    r = (p == 2) ? v[2] : r;
    r = (p == 3) ? v[3] : r;
    r = (p == 4) ? v[4] : r;
    return (p >= TOPK) ? 0x7fffffff : r;
}

// BRANCHLESS sorted insert (descending). Exact ties when inserted in
// increasing-index order (strict '>' keeps the earlier index).
__device__ __forceinline__ void bins5(float val, int idx, float v[TOPK], int id[TOPK]) {
    const bool p0 = val > v[0];
    const bool p1 = val > v[1];
    const bool p2 = val > v[2];
    const bool p3 = val > v[3];
    const bool p4 = val > v[4];
    v[4]  = p4 ? (p3 ? v[3]  : val) : v[4];
    id[4] = p4 ? (p3 ? id[3] : idx) : id[4];
    v[3]  = p3 ? (p2 ? v[2]  : val) : v[3];
    id[3] = p3 ? (p2 ? id[2] : idx) : id[3];
    v[2]  = p2 ? (p1 ? v[1]  : val) : v[2];
    id[2] = p2 ? (p1 ? id[1] : idx) : id[2];
    v[1]  = p1 ? (p0 ? v[0]  : val) : v[1];
    id[1] = p1 ? (p0 ? id[0] : idx) : id[1];
    v[0]  = p0 ? val  : v[0];
    id[0] = p0 ? idx  : id[0];
}

// Index-aware branchless insert (arrival order not monotone).
__device__ __forceinline__ void bins5_tie(float val, int idx, float v[TOPK], int id[TOPK]) {
    bool p[TOPK];
    #pragma unroll
    for (int j = 0; j < TOPK; ++j)
        p[j] = better(val, idx, v[j], id[j]);
    v[4]  = p[4] ? (p[3] ? v[3]  : val) : v[4];
    id[4] = p[4] ? (p[3] ? id[3] : idx) : id[4];
    v[3]  = p[3] ? (p[2] ? v[2]  : val) : v[3];
    id[3] = p[3] ? (p[2] ? id[2] : idx) : id[3];
    v[2]  = p[2] ? (p[1] ? v[1]  : val) : v[2];
    id[2] = p[2] ? (p[1] ? id[1] : idx) : id[2];
    v[1]  = p[1] ? (p[0] ? v[0]  : val) : v[1];
    id[1] = p[1] ? (p[0] ? id[0] : idx) : id[1];
    v[0]  = p[0] ? val  : v[0];
    id[0] = p[0] ? idx  : id[0];
}

// Warp argmax with index tie-break; winner broadcast to all lanes.
__device__ __forceinline__ void warp_argmax(float& cv, int& ci) {
    #pragma unroll
    for (int off = 16; off > 0; off >>= 1) {
        const float ov = __shfl_down_sync(FULLMASK, cv, off);
        const int   oi = __shfl_down_sync(FULLMASK, ci, off);
        if (better(ov, oi, cv, ci)) { cv = ov; ci = oi; }
    }
    cv = __shfl_sync(FULLMASK, cv, 0);
    ci = __shfl_sync(FULLMASK, ci, 0);
}

// Warp merge of 32 sorted 5-lists -> warp top-5. Winning lane calls emit.
template <typename EMIT>
__device__ __forceinline__ void warp_top5(const float v[TOPK], const int id[TOPK], EMIT emit) {
    int p = 0;
    #pragma unroll
    for (int r = 0; r < TOPK; ++r) {
        const float mv = get5f(v, p); const int mi = get5i(id, p);
        float cv = mv; int ci = mi;
        warp_argmax(cv, ci);
        if (mv == cv && mi == ci) {          // unique among real candidates
            ++p;
            emit(r, cv, ci);
        }
    }
}

// ---------------------------------------------------------------------------
// Fused kernel. Hot loop: 8 front-batched LDG.128 (true MLP=8, enabled by
// __launch_bounds__(256,4) register headroom), 8 zero STG.128, then
// 2 x (15 FMNMX group-of-16 max + 1 branchless insert). Candidates are
// (groupmax, groupbase) over CONTIGUOUS 16-element groups. Last block of each
// row reduces 1280 group candidates -> top-5 groups, re-reads those 80
// elements from x, exact top-5 of 80, scatters 1.0.  grid = 4096, block = 256.
// ---------------------------------------------------------------------------
__global__ __launch_bounds__(THREADS, 4)
void wta_fused(const float* __restrict__ x, float* __restrict__ out) {
    const int b    = blockIdx.x;
    const int row  = b >> 5;            // / BLOCKS_PER_ROW
    const int seg  = b & 31;            // % BLOCKS_PER_ROW
    const int t    = threadIdx.x;
    const int warp = t >> 5;
    const int lane = t & 31;

    const size_t base = (size_t)row * ROW_N + (size_t)seg * SEG_N;
    const float4* __restrict__ xv = (const float4*)(x + base);
    float4* __restrict__       ov = (float4*)(out + base);

    float v[TOPK]; int id[TOPK];
    #pragma unroll
    for (int j = 0; j < TOPK; ++j) { v[j] = -INFINITY; id[j] = 0x7fffffff; }

    // Thread t owns contiguous float4 quads at 4t..4t+3 (warp: 2048B coalesced).
    // All 8 loads issued first (MLP=8), then 8 independent zero stores.
    float4 d[VEC];
    #pragma unroll
    for (int k = 0; k < VEC; ++k)
        d[k] = __ldcs(&xv[(k >> 2) * 4 * THREADS + 4 * t + (k & 3)]);

    const float4 z = make_float4(0.f, 0.f, 0.f, 0.f);
    #pragma unroll
    for (int k = 0; k < VEC; ++k)
        __stcs(&ov[(k >> 2) * 4 * THREADS + 4 * t + (k & 3)], z);

    // Two groups of 16 contiguous elements -> 15 FMNMX + 1 insert each.
    #pragma unroll
    for (int g = 0; g < GROUPS; ++g) {
        const float4 a = d[4 * g], c = d[4 * g + 1], e = d[4 * g + 2], f = d[4 * g + 3];
        const float m0 = fmaxf(fmaxf(a.x, a.y), fmaxf(a.z, a.w));
        const float m1 = fmaxf(fmaxf(c.x, c.y), fmaxf(c.z, c.w));
        const float m2 = fmaxf(fmaxf(e.x, e.y), fmaxf(e.z, e.w));
        const float m3 = fmaxf(fmaxf(f.x, f.y), fmaxf(f.z, f.w));
        const float gm = fmaxf(fmaxf(m0, m1), fmaxf(m2, m3));
        const int gbase = seg * SEG_N + (g * 4 * THREADS + 4 * t) * 4;
        bins5(gm, gbase, v, id);          // one insert per 16 elements
    }

    // Warp merge -> 5 group candidates per warp straight to scratch.
    const int wbase = ((row * BLOCKS_PER_ROW + seg) * WARPS + warp) * TOPK;
    warp_top5(v, id, [&](int r, float bv, int bi) {
        g_cand_val[wbase + r] = bv;
        g_cand_idx[wbase + r] = bi;
    });

    // ---- last block of this row closes it -------------------------------
    __threadfence();                       // candidate stores -> device scope
    __shared__ int s_last;
    __syncthreads();
    if (t == 0) {
        const int old = atomicAdd(&g_row_cnt[row], 1);
        s_last = (old == BLOCKS_PER_ROW - 1);
    }
    __syncthreads();
    if (!s_last) return;
    if (t == 0) g_row_cnt[row] = 0;        // self-reset: graph-replay safe

    // Reduce this row's 1280 group candidates -> top-5 GROUPS.
    float rv[TOPK]; int ri[TOPK];
    #pragma unroll
    for (int j = 0; j < TOPK; ++j) { rv[j] = -INFINITY; ri[j] = 0x7fffffff; }

    const int cbase = row * CAND_PER_ROW;
    #pragma unroll
    for (int e = t; e < CAND_PER_ROW; e += THREADS)
        bins5_tie(__ldcg(&g_cand_val[cbase + e]),     // bypass L1: other SMs wrote
                  __ldcg(&g_cand_idx[cbase + e]), rv, ri);

    __shared__ float wv[WARPS * TOPK];
    __shared__ int   wi[WARPS * TOPK];
    __shared__ int   s_win[TOPK];
    warp_top5(rv, ri, [&](int r, float bv, int bi) {
        wv[warp * TOPK + r] = bv;
        wi[warp * TOPK + r] = bi;
    });
    __syncthreads();

    if (warp == 0) {
        float fv[TOPK]; int fi[TOPK];
        #pragma unroll
        for (int j = 0; j < TOPK; ++j) { fv[j] = -INFINITY; fi[j] = 0x7fffffff; }
        if (lane < WARPS * TOPK)
            bins5_tie(wv[lane], wi[lane], fv, fi);
        if (lane + 32 < WARPS * TOPK)
            bins5_tie(wv[lane + 32], wi[lane + 32], fv, fi);

        // Top-5 groups' base indices -> s_win.
        warp_top5(fv, fi, [&](int r, float bv, int bi) {
            s_win[r] = bi;
        });
        __syncwarp();

        // Expand the 5 winning groups: 80 elements, three slots per lane.
        const float* __restrict__ xr = x + (size_t)row * ROW_N;
        float ev[3]; int ei[3];
        #pragma unroll
        for (int s = 0; s < 3; ++s) {
            const int l = lane + 32 * s;
            if (l < EXP_N) {
                ei[s] = s_win[l >> 4] + (l & 15);
                ev[s] = __ldcg(&xr[ei[s]]);
            } else {
                ei[s] = 0x7fffffff;
                ev[s] = -INFINITY;
            }
        }

        // 5 rounds of warp argmax with exact tie rules; lane 0 scatters.
        #pragma unroll
        for (int r = 0; r < TOPK; ++r) {
            float mv = ev[0]; int mi = ei[0];
            if (better(ev[1], ei[1], mv, mi)) { mv = ev[1]; mi = ei[1]; }
            if (better(ev[2], ei[2], mv, mi)) { mv = ev[2]; mi = ei[2]; }
            float cv = mv; int ci = mi;
            warp_argmax(cv, ci);
            #pragma unroll
            for (int s = 0; s < 3; ++s)
                if (ci == ei[s]) ev[s] = -INFINITY;    // remove winner (unique idx)
            if (lane == 0)
                out[(size_t)row * ROW_N + ci] = 1.0f;
        }
    }
}

// ---------------------------------------------------------------------------
extern "C" void kernel_launch(void* const* d_in, const int* in_sizes, int n_in,
                              void* d_out, int out_size) {
    const float* x = (const float*)d_in[0];
    float* out = (float*)d_out;
    wta_fused<<<ROWS * BLOCKS_PER_ROW, THREADS>>>(x, out);
}

// round 14
// speedup vs baseline: 1.2673x; 1.2673x over previous
#include <cuda_runtime.h>
#include <cstdint>

#define ROWS            128
#define ROW_N           262144                     // 256*32*32
#define BLOCKS_PER_ROW  32
#define SEG_N           (ROW_N / BLOCKS_PER_ROW)   // 8192 elements per block
#define THREADS         256
#define WARPS           (THREADS / 32)             // 8
#define VEC             (SEG_N / 4 / THREADS)      // 8 float4 per thread
#define GSIZE           16                         // elements per prescreen group
#define GROUPS          2                          // groups of 16 per thread
#define STRIDE_ELEMS    (THREADS * 4)              // 1024: element stride between
                                                   // a group's float4 members
#define TOPK            5
#define EXP_N           (TOPK * GSIZE)             // 80 elements to expand
#define CAND_PER_ROW    (BLOCKS_PER_ROW * WARPS * TOPK)   // 1280 group candidates

#define FULLMASK 0xFFFFFFFFu

// Scratch (no cudaMalloc allowed). Zero-initialized device globals.
__device__ float g_cand_val[ROWS * CAND_PER_ROW];   // group max
__device__ int   g_cand_idx[ROWS * CAND_PER_ROW];   // group base index (row-relative)
__device__ int   g_row_cnt[ROWS];                   // last-block-closes-row counters

// larger value wins; equal value -> smaller index wins (jax.lax.top_k stability).
__device__ __forceinline__ bool better(float v, int i, float bv, int bi) {
    return (v > bv) || (v == bv && i < bi);
}

// Register-resident 5-way select (avoids local-memory spill from dynamic index).
__device__ __forceinline__ float get5f(const float v[TOPK], int p) {
    float r = (p == 0) ? v[0] : v[1];
    r = (p == 2) ? v[2] : r;
    r = (p == 3) ? v[3] : r;
    r = (p == 4) ? v[4] : r;
    return (p >= TOPK) ? -INFINITY : r;
}
__device__ __forceinline__ int get5i(const int v[TOPK], int p) {
    int r = (p == 0) ? v[0] : v[1];
    r = (p == 2) ? v[2] : r;
    r = (p == 3) ? v[3] : r;
    r = (p == 4) ? v[4] : r;
    return (p >= TOPK) ? 0x7fffffff : r;
}

// BRANCHLESS sorted insert (descending). Exact ties when inserted in
// increasing-index order (strict '>' keeps the earlier index).
__device__ __forceinline__ void bins5(float val, int idx, float v[TOPK], int id[TOPK]) {
    const bool p0 = val > v[0];
    const bool p1 = val > v[1];
    const bool p2 = val > v[2];
    const bool p3 = val > v[3];
    const bool p4 = val > v[4];
    v[4]  = p4 ? (p3 ? v[3]  : val) : v[4];
    id[4] = p4 ? (p3 ? id[3] : idx) : id[4];
    v[3]  = p3 ? (p2 ? v[2]  : val) : v[3];
    id[3] = p3 ? (p2 ? id[2] : idx) : id[3];
    v[2]  = p2 ? (p1 ? v[1]  : val) : v[2];
    id[2] = p2 ? (p1 ? id[1] : idx) : id[2];
    v[1]  = p1 ? (p0 ? v[0]  : val) : v[1];
    id[1] = p1 ? (p0 ? id[0] : idx) : id[1];
    v[0]  = p0 ? val  : v[0];
    id[0] = p0 ? idx  : id[0];
}

// Index-aware branchless insert (arrival order not monotone).
__device__ __forceinline__ void bins5_tie(float val, int idx, float v[TOPK], int id[TOPK]) {
    bool p[TOPK];
    #pragma unroll
    for (int j = 0; j < TOPK; ++j)
        p[j] = better(val, idx, v[j], id[j]);
    v[4]  = p[4] ? (p[3] ? v[3]  : val) : v[4];
    id[4] = p[4] ? (p[3] ? id[3] : idx) : id[4];
    v[3]  = p[3] ? (p[2] ? v[2]  : val) : v[3];
    id[3] = p[3] ? (p[2] ? id[2] : idx) : id[3];
    v[2]  = p[2] ? (p[1] ? v[1]  : val) : v[2];
    id[2] = p[2] ? (p[1] ? id[1] : idx) : id[2];
    v[1]  = p[1] ? (p[0] ? v[0]  : val) : v[1];
    id[1] = p[1] ? (p[0] ? id[0] : idx) : id[1];
    v[0]  = p[0] ? val  : v[0];
    id[0] = p[0] ? idx  : id[0];
}

// Warp argmax with index tie-break; winner broadcast to all lanes.
__device__ __forceinline__ void warp_argmax(float& cv, int& ci) {
    #pragma unroll
    for (int off = 16; off > 0; off >>= 1) {
        const float ov = __shfl_down_sync(FULLMASK, cv, off);
        const int   oi = __shfl_down_sync(FULLMASK, ci, off);
        if (better(ov, oi, cv, ci)) { cv = ov; ci = oi; }
    }
    cv = __shfl_sync(FULLMASK, cv, 0);
    ci = __shfl_sync(FULLMASK, ci, 0);
}

// Warp merge of 32 sorted 5-lists -> warp top-5. Winning lane calls emit.
template <typename EMIT>
__device__ __forceinline__ void warp_top5(const float v[TOPK], const int id[TOPK], EMIT emit) {
    int p = 0;
    #pragma unroll
    for (int r = 0; r < TOPK; ++r) {
        const float mv = get5f(v, p); const int mi = get5i(id, p);
        float cv = mv; int ci = mi;
        warp_argmax(cv, ci);
        if (mv == cv && mi == ci) {          // unique among real candidates
            ++p;
            emit(r, cv, ci);
        }
    }
}

// ---------------------------------------------------------------------------
// Fused kernel. Hot loop: 8 front-batched PERFECTLY-COALESCED LDG.128
// (k*THREADS+t addressing, 512B/warp/instr; MLP=8 via launch_bounds reg
// headroom), 8 zero STG.128, then 2 x (15 FMNMX + 1 insert) over STRIDED
// groups of 16: group g of thread t = { gbase + k*1024 + c, k,c in 0..3 },
// gbase = seg*8192 + g*4096 + t*4. Groups are disjoint with a fixed mapping,
// preserving prescreen-then-expand exactness. Last block of each row reduces
// 1280 group candidates -> top-5 groups, re-reads those 80 elements from x,
// exact top-5 of 80, scatters 1.0.  grid = 4096, block = 256.
// ---------------------------------------------------------------------------
__global__ __launch_bounds__(THREADS, 4)
void wta_fused(const float* __restrict__ x, float* __restrict__ out) {
    const int b    = blockIdx.x;
    const int row  = b >> 5;            // / BLOCKS_PER_ROW
    const int seg  = b & 31;            // % BLOCKS_PER_ROW
    const int t    = threadIdx.x;
    const int warp = t >> 5;
    const int lane = t & 31;

    const size_t base = (size_t)row * ROW_N + (size_t)seg * SEG_N;
    const float4* __restrict__ xv = (const float4*)(x + base);
    float4* __restrict__       ov = (float4*)(out + base);

    float v[TOPK]; int id[TOPK];
    #pragma unroll
    for (int j = 0; j < TOPK; ++j) { v[j] = -INFINITY; id[j] = 0x7fffffff; }

    // All 8 coalesced loads issued first (MLP=8), then 8 independent stores.
    float4 d[VEC];
    #pragma unroll
    for (int k = 0; k < VEC; ++k)
        d[k] = __ldcs(&xv[k * THREADS + t]);

    const float4 z = make_float4(0.f, 0.f, 0.f, 0.f);
    #pragma unroll
    for (int k = 0; k < VEC; ++k)
        __stcs(&ov[k * THREADS + t], z);

    // Two strided groups of 16 -> 15 FMNMX + 1 insert each.
    #pragma unroll
    for (int g = 0; g < GROUPS; ++g) {
        const float4 a = d[4 * g], c = d[4 * g + 1], e = d[4 * g + 2], f = d[4 * g + 3];
        const float m0 = fmaxf(fmaxf(a.x, a.y), fmaxf(a.z, a.w));
        const float m1 = fmaxf(fmaxf(c.x, c.y), fmaxf(c.z, c.w));
        const float m2 = fmaxf(fmaxf(e.x, e.y), fmaxf(e.z, e.w));
        const float m3 = fmaxf(fmaxf(f.x, f.y), fmaxf(f.z, f.w));
        const float gm = fmaxf(fmaxf(m0, m1), fmaxf(m2, m3));
        // Group base: first member's row-relative element index.
        const int gbase = seg * SEG_N + g * 4 * STRIDE_ELEMS + t * 4;
        bins5(gm, gbase, v, id);          // one insert per 16 elements
    }

    // Warp merge -> 5 group candidates per warp straight to scratch.
    const int wbase = ((row * BLOCKS_PER_ROW + seg) * WARPS + warp) * TOPK;
    warp_top5(v, id, [&](int r, float bv, int bi) {
        g_cand_val[wbase + r] = bv;
        g_cand_idx[wbase + r] = bi;
    });

    // ---- last block of this row closes it -------------------------------
    __threadfence();                       // candidate stores -> device scope
    __shared__ int s_last;
    __syncthreads();
    if (t == 0) {
        const int old = atomicAdd(&g_row_cnt[row], 1);
        s_last = (old == BLOCKS_PER_ROW - 1);
    }
    __syncthreads();
    if (!s_last) return;
    if (t == 0) g_row_cnt[row] = 0;        // self-reset: graph-replay safe

    // Reduce this row's 1280 group candidates -> top-5 GROUPS.
    float rv[TOPK]; int ri[TOPK];
    #pragma unroll
    for (int j = 0; j < TOPK; ++j) { rv[j] = -INFINITY; ri[j] = 0x7fffffff; }

    const int cbase = row * CAND_PER_ROW;
    #pragma unroll
    for (int e = t; e < CAND_PER_ROW; e += THREADS)
        bins5_tie(__ldcg(&g_cand_val[cbase + e]),     // bypass L1: other SMs wrote
                  __ldcg(&g_cand_idx[cbase + e]), rv, ri);

    __shared__ float wv[WARPS * TOPK];
    __shared__ int   wi[WARPS * TOPK];
    __shared__ int   s_win[TOPK];
    warp_top5(rv, ri, [&](int r, float bv, int bi) {
        wv[warp * TOPK + r] = bv;
        wi[warp * TOPK + r] = bi;
    });
    __syncthreads();

    if (warp == 0) {
        float fv[TOPK]; int fi[TOPK];
        #pragma unroll
        for (int j = 0; j < TOPK; ++j) { fv[j] = -INFINITY; fi[j] = 0x7fffffff; }
        if (lane < WARPS * TOPK)
            bins5_tie(wv[lane], wi[lane], fv, fi);
        if (lane + 32 < WARPS * TOPK)
            bins5_tie(wv[lane + 32], wi[lane + 32], fv, fi);

        // Top-5 groups' base indices -> s_win.
        warp_top5(fv, fi, [&](int r, float bv, int bi) {
            s_win[r] = bi;
        });
        __syncwarp();

        // Expand the 5 winning groups: member k,c of group base B is
        // B + k*STRIDE_ELEMS + c. 80 elements, three slots per lane.
        const float* __restrict__ xr = x + (size_t)row * ROW_N;
        float ev[3]; int ei[3];
        #pragma unroll
        for (int s = 0; s < 3; ++s) {
            const int l = lane + 32 * s;
            if (l < EXP_N) {
                const int w = l & 15;                      // within-group slot
                ei[s] = s_win[l >> 4] + (w >> 2) * STRIDE_ELEMS + (w & 3);
                ev[s] = __ldcg(&xr[ei[s]]);
            } else {
                ei[s] = 0x7fffffff;
                ev[s] = -INFINITY;
            }
        }

        // 5 rounds of warp argmax with exact tie rules; lane 0 scatters.
        #pragma unroll
        for (int r = 0; r < TOPK; ++r) {
            float mv = ev[0]; int mi = ei[0];
            if (better(ev[1], ei[1], mv, mi)) { mv = ev[1]; mi = ei[1]; }
            if (better(ev[2], ei[2], mv, mi)) { mv = ev[2]; mi = ei[2]; }
            float cv = mv; int ci = mi;
            warp_argmax(cv, ci);
            #pragma unroll
            for (int s = 0; s < 3; ++s)
                if (ci == ei[s]) ev[s] = -INFINITY;    // remove winner (unique idx)
            if (lane == 0)
                out[(size_t)row * ROW_N + ci] = 1.0f;
        }
    }
}

// ---------------------------------------------------------------------------
extern "C" void kernel_launch(void* const* d_in, const int* in_sizes, int n_in,
                              void* d_out, int out_size) {
    const float* x = (const float*)d_in[0];
    float* out = (float*)d_out;
    wta_fused<<<ROWS * BLOCKS_PER_ROW, THREADS>>>(x, out);
}

// round 15
// speedup vs baseline: 1.2747x; 1.0058x over previous
#include <cuda_runtime.h>
#include <cstdint>

#define ROWS            128
#define ROW_N           262144                     // 256*32*32
#define BLOCKS_PER_ROW  32
#define SEG_N           (ROW_N / BLOCKS_PER_ROW)   // 8192 elements per block
#define SEG_BYTES       (SEG_N * 4)                // 32768 bytes per block
#define THREADS         256
#define WARPS           (THREADS / 32)             // 8
#define VEC             (SEG_N / 4 / THREADS)      // 8 float4 per thread
#define GSIZE           16                         // elements per prescreen group
#define GROUPS          2                          // groups of 16 per thread
#define STRIDE_ELEMS    (THREADS * 4)              // 1024: element stride between
                                                   // a group's float4 members
#define TOPK            5
#define EXP_N           (TOPK * GSIZE)             // 80 elements to expand
#define CAND_PER_ROW    (BLOCKS_PER_ROW * WARPS * TOPK)   // 1280 group candidates

#define ZBUF_BYTES      16384                      // SMEM zero buffer (16 KB)
#define ZBUF_F4         (ZBUF_BYTES / 16)          // 1024 float4

#define FULLMASK 0xFFFFFFFFu

// Scratch (no cudaMalloc allowed). Zero-initialized device globals.
__device__ float g_cand_val[ROWS * CAND_PER_ROW];   // group max
__device__ int   g_cand_idx[ROWS * CAND_PER_ROW];   // group base index (row-relative)
__device__ int   g_row_cnt[ROWS];                   // last-block-closes-row counters

// larger value wins; equal value -> smaller index wins (jax.lax.top_k stability).
__device__ __forceinline__ bool better(float v, int i, float bv, int bi) {
    return (v > bv) || (v == bv && i < bi);
}

// Register-resident 5-way select (avoids local-memory spill from dynamic index).
__device__ __forceinline__ float get5f(const float v[TOPK], int p) {
    float r = (p == 0) ? v[0] : v[1];
    r = (p == 2) ? v[2] : r;
    r = (p == 3) ? v[3] : r;
    r = (p == 4) ? v[4] : r;
    return (p >= TOPK) ? -INFINITY : r;
}
__device__ __forceinline__ int get5i(const int v[TOPK], int p) {
    int r = (p == 0) ? v[0] : v[1];
    r = (p == 2) ? v[2] : r;
    r = (p == 3) ? v[3] : r;
    r = (p == 4) ? v[4] : r;
    return (p >= TOPK) ? 0x7fffffff : r;
}

// BRANCHLESS sorted insert (descending). Exact ties when inserted in
// increasing-index order (strict '>' keeps the earlier index).
__device__ __forceinline__ void bins5(float val, int idx, float v[TOPK], int id[TOPK]) {
    const bool p0 = val > v[0];
    const bool p1 = val > v[1];
    const bool p2 = val > v[2];
    const bool p3 = val > v[3];
    const bool p4 = val > v[4];
    v[4]  = p4 ? (p3 ? v[3]  : val) : v[4];
    id[4] = p4 ? (p3 ? id[3] : idx) : id[4];
    v[3]  = p3 ? (p2 ? v[2]  : val) : v[3];
    id[3] = p3 ? (p2 ? id[2] : idx) : id[3];
    v[2]  = p2 ? (p1 ? v[1]  : val) : v[2];
    id[2] = p2 ? (p1 ? id[1] : idx) : id[2];
    v[1]  = p1 ? (p0 ? v[0]  : val) : v[1];
    id[1] = p1 ? (p0 ? id[0] : idx) : id[1];
    v[0]  = p0 ? val  : v[0];
    id[0] = p0 ? idx  : id[0];
}

// Index-aware branchless insert (arrival order not monotone).
__device__ __forceinline__ void bins5_tie(float val, int idx, float v[TOPK], int id[TOPK]) {
    bool p[TOPK];
    #pragma unroll
    for (int j = 0; j < TOPK; ++j)
        p[j] = better(val, idx, v[j], id[j]);
    v[4]  = p[4] ? (p[3] ? v[3]  : val) : v[4];
    id[4] = p[4] ? (p[3] ? id[3] : idx) : id[4];
    v[3]  = p[3] ? (p[2] ? v[2]  : val) : v[3];
    id[3] = p[3] ? (p[2] ? id[2] : idx) : id[3];
    v[2]  = p[2] ? (p[1] ? v[1]  : val) : v[2];
    id[2] = p[2] ? (p[1] ? id[1] : idx) : id[2];
    v[1]  = p[1] ? (p[0] ? v[0]  : val) : v[1];
    id[1] = p[1] ? (p[0] ? id[0] : idx) : id[1];
    v[0]  = p[0] ? val  : v[0];
    id[0] = p[0] ? idx  : id[0];
}

// Warp argmax with index tie-break; winner broadcast to all lanes.
__device__ __forceinline__ void warp_argmax(float& cv, int& ci) {
    #pragma unroll
    for (int off = 16; off > 0; off >>= 1) {
        const float ov = __shfl_down_sync(FULLMASK, cv, off);
        const int   oi = __shfl_down_sync(FULLMASK, ci, off);
        if (better(ov, oi, cv, ci)) { cv = ov; ci = oi; }
    }
    cv = __shfl_sync(FULLMASK, cv, 0);
    ci = __shfl_sync(FULLMASK, ci, 0);
}

// Warp merge of 32 sorted 5-lists -> warp top-5. Winning lane calls emit.
template <typename EMIT>
__device__ __forceinline__ void warp_top5(const float v[TOPK], const int id[TOPK], EMIT emit) {
    int p = 0;
    #pragma unroll
    for (int r = 0; r < TOPK; ++r) {
        const float mv = get5f(v, p); const int mi = get5i(id, p);
        float cv = mv; int ci = mi;
        warp_argmax(cv, ci);
        if (mv == cv && mi == ci) {          // unique among real candidates
            ++p;
            emit(r, cv, ci);
        }
    }
}

// ---------------------------------------------------------------------------
// Fused kernel. Loads: 8 front-batched perfectly-coalesced LDG.128 (MLP=8).
// Zero-fill of out: TMA bulk S2G from a 16KB SMEM zero buffer (2 x 16KB per
// block) -- zero L1tex/MSHR usage, streams via the TMA engine. Compute:
// 2 x (15 FMNMX + 1 insert) over strided 16-elem groups. Each block waits for
// its bulk-store WRITE completion before arriving on the row counter, so the
// closer's 1.0 stores are ordered after all zero stores of the row. Last block
// per row reduces 1280 group candidates -> top-5 groups, re-reads 80 elems,
// exact top-5, scatters 1.0.  grid = 4096, block = 256.
// ---------------------------------------------------------------------------
__global__ __launch_bounds__(THREADS, 4)
void wta_fused(const float* __restrict__ x, float* __restrict__ out) {
    const int b    = blockIdx.x;
    const int row  = b >> 5;            // / BLOCKS_PER_ROW
    const int seg  = b & 31;            // % BLOCKS_PER_ROW
    const int t    = threadIdx.x;
    const int warp = t >> 5;
    const int lane = t & 31;

    __shared__ float4 zbuf[ZBUF_F4];    // 16 KB of zeros (TMA source)

    const size_t base = (size_t)row * ROW_N + (size_t)seg * SEG_N;
    const float4* __restrict__ xv = (const float4*)(x + base);

    float v[TOPK]; int id[TOPK];
    #pragma unroll
    for (int j = 0; j < TOPK; ++j) { v[j] = -INFINITY; id[j] = 0x7fffffff; }

    // All 8 coalesced loads issued first (MLP=8).
    float4 d[VEC];
    #pragma unroll
    for (int k = 0; k < VEC; ++k)
        d[k] = __ldcs(&xv[k * THREADS + t]);

    // Fill the SMEM zero buffer while loads are in flight.
    const float4 z = make_float4(0.f, 0.f, 0.f, 0.f);
    #pragma unroll
    for (int k = 0; k < ZBUF_F4 / THREADS; ++k)
        zbuf[k * THREADS + t] = z;
    __syncthreads();

    // One thread launches the 32KB zero-fill via TMA bulk S2G (2 x 16KB).
    if (t == 0) {
        asm volatile("fence.proxy.async.shared::cta;" ::: "memory");
        const uint32_t zaddr =
            (uint32_t)__cvta_generic_to_shared(&zbuf[0]);
        float* gdst = out + base;
        asm volatile(
            "cp.async.bulk.global.shared::cta.bulk_group [%0], [%1], %2;"
            :: "l"(gdst), "r"(zaddr), "n"(ZBUF_BYTES) : "memory");
        asm volatile(
            "cp.async.bulk.global.shared::cta.bulk_group [%0], [%1], %2;"
            :: "l"(gdst + SEG_N / 2), "r"(zaddr), "n"(ZBUF_BYTES) : "memory");
        asm volatile("cp.async.bulk.commit_group;" ::: "memory");
    }

    // Two strided groups of 16 -> 15 FMNMX + 1 insert each.
    #pragma unroll
    for (int g = 0; g < GROUPS; ++g) {
        const float4 a = d[4 * g], c = d[4 * g + 1], e = d[4 * g + 2], f = d[4 * g + 3];
        const float m0 = fmaxf(fmaxf(a.x, a.y), fmaxf(a.z, a.w));
        const float m1 = fmaxf(fmaxf(c.x, c.y), fmaxf(c.z, c.w));
        const float m2 = fmaxf(fmaxf(e.x, e.y), fmaxf(e.z, e.w));
        const float m3 = fmaxf(fmaxf(f.x, f.y), fmaxf(f.z, f.w));
        const float gm = fmaxf(fmaxf(m0, m1), fmaxf(m2, m3));
        // Group base: first member's row-relative element index.
        const int gbase = seg * SEG_N + g * 4 * STRIDE_ELEMS + t * 4;
        bins5(gm, gbase, v, id);          // one insert per 16 elements
    }

    // Warp merge -> 5 group candidates per warp straight to scratch.
    const int wbase = ((row * BLOCKS_PER_ROW + seg) * WARPS + warp) * TOPK;
    warp_top5(v, id, [&](int r, float bv, int bi) {
        g_cand_val[wbase + r] = bv;
        g_cand_idx[wbase + r] = bi;
    });

    // ---- last block of this row closes it -------------------------------
    // Wait for OUR zero-stores' write completion BEFORE signaling: the
    // closer's 1.0 stores must be ordered after every zero store of the row.
    if (t == 0)
        asm volatile("cp.async.bulk.wait_group 0;" ::: "memory");
    __threadfence();                       // candidate stores -> device scope
    __shared__ int s_last;
    __syncthreads();                       // t0's wait precedes its atomicAdd
    if (t == 0) {
        const int old = atomicAdd(&g_row_cnt[row], 1);
        s_last = (old == BLOCKS_PER_ROW - 1);
    }
    __syncthreads();
    if (!s_last) return;
    if (t == 0) g_row_cnt[row] = 0;        // self-reset: graph-replay safe

    // Reduce this row's 1280 group candidates -> top-5 GROUPS.
    float rv[TOPK]; int ri[TOPK];
    #pragma unroll
    for (int j = 0; j < TOPK; ++j) { rv[j] = -INFINITY; ri[j] = 0x7fffffff; }

    const int cbase = row * CAND_PER_ROW;
    #pragma unroll
    for (int e = t; e < CAND_PER_ROW; e += THREADS)
        bins5_tie(__ldcg(&g_cand_val[cbase + e]),     // bypass L1: other SMs wrote
                  __ldcg(&g_cand_idx[cbase + e]), rv, ri);

    __shared__ float wv[WARPS * TOPK];
    __shared__ int   wi[WARPS * TOPK];
    __shared__ int   s_win[TOPK];
    warp_top5(rv, ri, [&](int r, float bv, int bi) {
        wv[warp * TOPK + r] = bv;
        wi[warp * TOPK + r] = bi;
    });
    __syncthreads();

    if (warp == 0) {
        float fv[TOPK]; int fi[TOPK];
        #pragma unroll
        for (int j = 0; j < TOPK; ++j) { fv[j] = -INFINITY; fi[j] = 0x7fffffff; }
        if (lane < WARPS * TOPK)
            bins5_tie(wv[lane], wi[lane], fv, fi);
        if (lane + 32 < WARPS * TOPK)
            bins5_tie(wv[lane + 32], wi[lane + 32], fv, fi);

        // Top-5 groups' base indices -> s_win.
        warp_top5(fv, fi, [&](int r, float bv, int bi) {
            s_win[r] = bi;
        });
        __syncwarp();

        // Expand the 5 winning groups: member k,c of group base B is
        // B + k*STRIDE_ELEMS + c. 80 elements, three slots per lane.
        const float* __restrict__ xr = x + (size_t)row * ROW_N;
        float ev[3]; int ei[3];
        #pragma unroll
        for (int s = 0; s < 3; ++s) {
            const int l = lane + 32 * s;
            if (l < EXP_N) {
                const int w = l & 15;                      // within-group slot
                ei[s] = s_win[l >> 4] + (w >> 2) * STRIDE_ELEMS + (w & 3);
                ev[s] = __ldcg(&xr[ei[s]]);
            } else {
                ei[s] = 0x7fffffff;
                ev[s] = -INFINITY;
            }
        }

        // 5 rounds of warp argmax with exact tie rules; lane 0 scatters.
        #pragma unroll
        for (int r = 0; r < TOPK; ++r) {
            float mv = ev[0]; int mi = ei[0];
            if (better(ev[1], ei[1], mv, mi)) { mv = ev[1]; mi = ei[1]; }
            if (better(ev[2], ei[2], mv, mi)) { mv = ev[2]; mi = ei[2]; }
            float cv = mv; int ci = mi;
            warp_argmax(cv, ci);
            #pragma unroll
            for (int s = 0; s < 3; ++s)
                if (ci == ei[s]) ev[s] = -INFINITY;    // remove winner (unique idx)
            if (lane == 0)
                out[(size_t)row * ROW_N + ci] = 1.0f;
        }
    }
}

// ---------------------------------------------------------------------------
extern "C" void kernel_launch(void* const* d_in, const int* in_sizes, int n_in,
                              void* d_out, int out_size) {
    const float* x = (const float*)d_in[0];
    float* out = (float*)d_out;
    wta_fused<<<ROWS * BLOCKS_PER_ROW, THREADS>>>(x, out);
}